// round 5
// baseline (speedup 1.0000x reference)
#include <cuda_runtime.h>
#include <math.h>

// Problem constants
#define B_   4
#define S_   2048
#define H_   12
#define D_   100
#define HID_ 1200
#define M_   (B_*S_)   // 8192

// Scratch (allocation-free rule: __device__ globals)
__device__ float g_q [B_*H_*S_*D_];
__device__ float g_k [B_*H_*S_*D_];
__device__ float g_v [B_*H_*S_*D_];
__device__ float g_ao[B_*H_*S_*D_];

// ---------------------------------------------------------------------------
// GEMM (TN): C[m,n] = sum_k A[m,k] * W[n,k]
// A: (M_, HID_) row-major, W: (HID_, HID_) row-major.
// 128x128x16 tiles, 256 threads, 8x8 microtile, double-buffered smem
// (1 __syncthreads per 16-K slice; global prefetch overlapped with compute).
//
// Fused-QKV variant: gridDim.z = 3, z selects weight + destination, output
// scattered into (b,h,s,d). Packs 1920 CTAs into full waves (7% tail waste
// vs 28% for three separate 640-CTA launches).
// ---------------------------------------------------------------------------
#define BM 128
#define BN 128
#define BKg 16

__device__ __forceinline__ void gemm_tn_body(
    const float* __restrict__ A, const float* __restrict__ W,
    float* __restrict__ dst, int qkv_mode)
{
    __shared__ __align__(16) float As[2][BKg][BM];
    __shared__ __align__(16) float Bs[2][BKg][BN];

    const int K = HID_, N = HID_;
    const int t  = threadIdx.x;
    const int m0 = blockIdx.y * BM;
    const int n0 = blockIdx.x * BN;

    // Tile load mapping: 128 rows x 16 cols = 512 float4 per array,
    // 2 per thread: row = t>>1, col segments seg and seg+8 (seg = (t&1)*4).
    const int ldRow = t >> 1;        // 0..127
    const int ldSeg = (t & 1) * 4;   // 0 or 4

    const int tm0 = (t >> 4) * 8;    // 16x16 thread grid, 8x8 each
    const int tn0 = (t & 15) * 8;

    float acc[8][8];
    #pragma unroll
    for (int i = 0; i < 8; i++)
        #pragma unroll
        for (int j = 0; j < 8; j++) acc[i][j] = 0.0f;

    const bool bValid = (n0 + ldRow) < N;
    const float* aPtr = A + (size_t)(m0 + ldRow) * K + ldSeg;
    const float* bPtr = W + (size_t)(n0 + ldRow) * K + ldSeg;

    float4 av0, av1, bv0, bv1;

    // Prime buffer 0
    av0 = *(const float4*)(aPtr);
    av1 = *(const float4*)(aPtr + 8);
    bv0 = make_float4(0.f, 0.f, 0.f, 0.f);
    bv1 = bv0;
    if (bValid) {
        bv0 = *(const float4*)(bPtr);
        bv1 = *(const float4*)(bPtr + 8);
    }
    {
        const float ae0[4] = {av0.x, av0.y, av0.z, av0.w};
        const float ae1[4] = {av1.x, av1.y, av1.z, av1.w};
        const float be0[4] = {bv0.x, bv0.y, bv0.z, bv0.w};
        const float be1[4] = {bv1.x, bv1.y, bv1.z, bv1.w};
        #pragma unroll
        for (int e = 0; e < 4; e++) {
            As[0][ldSeg + e][ldRow]     = ae0[e];
            As[0][ldSeg + 8 + e][ldRow] = ae1[e];
            Bs[0][ldSeg + e][ldRow]     = be0[e];
            Bs[0][ldSeg + 8 + e][ldRow] = be1[e];
        }
    }
    __syncthreads();

    int buf = 0;
    for (int k0 = 0; k0 < K; k0 += BKg) {
        const bool hasNext = (k0 + BKg) < K;
        if (hasNext) {
            av0 = *(const float4*)(aPtr + k0 + BKg);
            av1 = *(const float4*)(aPtr + k0 + BKg + 8);
            if (bValid) {
                bv0 = *(const float4*)(bPtr + k0 + BKg);
                bv1 = *(const float4*)(bPtr + k0 + BKg + 8);
            }
        }

        #pragma unroll
        for (int kk = 0; kk < BKg; kk++) {
            float ra[8], rb[8];
            *(float4*)(ra)     = *(const float4*)&As[buf][kk][tm0];
            *(float4*)(ra + 4) = *(const float4*)&As[buf][kk][tm0 + 4];
            *(float4*)(rb)     = *(const float4*)&Bs[buf][kk][tn0];
            *(float4*)(rb + 4) = *(const float4*)&Bs[buf][kk][tn0 + 4];
            #pragma unroll
            for (int i = 0; i < 8; i++)
                #pragma unroll
                for (int j = 0; j < 8; j++)
                    acc[i][j] = fmaf(ra[i], rb[j], acc[i][j]);
        }

        if (hasNext) {
            const int nb = buf ^ 1;
            const float ae0[4] = {av0.x, av0.y, av0.z, av0.w};
            const float ae1[4] = {av1.x, av1.y, av1.z, av1.w};
            const float be0[4] = {bv0.x, bv0.y, bv0.z, bv0.w};
            const float be1[4] = {bv1.x, bv1.y, bv1.z, bv1.w};
            #pragma unroll
            for (int e = 0; e < 4; e++) {
                As[nb][ldSeg + e][ldRow]     = ae0[e];
                As[nb][ldSeg + 8 + e][ldRow] = ae1[e];
                Bs[nb][ldSeg + e][ldRow]     = be0[e];
                Bs[nb][ldSeg + 8 + e][ldRow] = be1[e];
            }
        }
        __syncthreads();
        buf ^= 1;
    }

    // Store
    #pragma unroll
    for (int i = 0; i < 8; i++) {
        const int m = m0 + tm0 + i;
        #pragma unroll
        for (int j = 0; j < 8; j++) {
            const int n = n0 + tn0 + j;
            if (n < N) {
                const float v = acc[i][j];
                if (qkv_mode) {
                    const int b = m >> 11;          // S_ = 2048
                    const int s = m & (S_ - 1);
                    const int h = n / D_;
                    const int d = n - h * D_;
                    dst[(((size_t)(b * H_ + h)) * S_ + s) * D_ + d] = v;
                } else {
                    dst[(size_t)m * N + n] = v;
                }
            }
        }
    }
}

// Fused QKV: gridDim.z = 3 selects {wq->g_q, wk->g_k, wv->g_v}
__global__ __launch_bounds__(256)
void gemm_qkv_kernel(const float* __restrict__ A,
                     const float* __restrict__ wq,
                     const float* __restrict__ wk,
                     const float* __restrict__ wv,
                     float* __restrict__ qdst,
                     float* __restrict__ kdst,
                     float* __restrict__ vdst)
{
    const int z = blockIdx.z;
    const float* W = (z == 0) ? wq : (z == 1) ? wk : wv;
    float* dst     = (z == 0) ? qdst : (z == 1) ? kdst : vdst;
    gemm_tn_body(A, W, dst, 1);
}

// Plain single GEMM (output projection)
__global__ __launch_bounds__(256)
void gemm_tn_kernel(const float* __restrict__ A, const float* __restrict__ W,
                    float* __restrict__ dst)
{
    gemm_tn_body(A, W, dst, 0);
}

// ---------------------------------------------------------------------------
// Flash attention (fp32, online softmax).
// grid: (S_/64, B_*H_), block: 256 threads.
// S = qk * (10/L) + alibi/L + mask   (sqrt(D)=10, L = layer_index+1)
// Output written in (b,h,s,d) C-order == the reference's raw reshape layout.
//
// Smem layouts (hot-loop accesses LDS.128/STS.128, bank behavior verified):
//  Qt,Kt : transposed, leading dim 68 (16B-aligned float4 microtile bases)
//  Vs    : rows of 4 padded 28-float groups (stride 112); lane cgrp's 25
//          columns (d = cgrp*25 ..+24) start at float offset cgrp*28
//  Ss    : 64x68 score tile (stride 68 -> STS.128 epilogue conflict-free)
// ---------------------------------------------------------------------------
#define LDT  68   // transposed Q/K smem leading dim
#define LDS_ 68   // score tile leading dim
#define VLD  112  // V smem row stride (4 groups x 28)
#define NF4  (64 * D_ / 4)   // 1600 float4 per 64x100 tile

__global__ __launch_bounds__(256)
void flash_kernel(const float* __restrict__ alibi,
                  const float* __restrict__ mask,
                  const int*   __restrict__ li_ptr)
{
    extern __shared__ float sm[];
    float* Qt   = sm;                   // [100][68]
    float* Kt   = Qt + D_ * LDT;        // [100][68]
    float* Vs   = Kt + D_ * LDT;        // [64][112]
    float* Ss   = Vs + 64 * VLD;        // [64][68]
    float* bias = Ss + 64 * LDS_;       // [64]

    const int t  = threadIdx.x;
    const int bh = blockIdx.y;
    const int b  = bh / H_;
    const int q0 = blockIdx.x * 64;

    const float* qbase = g_q + (size_t)bh * S_ * D_;
    const float* kbase = g_k + (size_t)bh * S_ * D_;
    const float* vbase = g_v + (size_t)bh * S_ * D_;

    // Load Q tile transposed via LDG.128: Qt[d][i]
    for (int idx4 = t; idx4 < NF4; idx4 += 256) {
        const int row = idx4 / 25;          // query row in tile
        const int d0  = (idx4 - row * 25) * 4;
        const float4 qv = *(const float4*)(qbase + (size_t)(q0 + row) * D_ + d0);
        Qt[(d0+0) * LDT + row] = qv.x;
        Qt[(d0+1) * LDT + row] = qv.y;
        Qt[(d0+2) * LDT + row] = qv.z;
        Qt[(d0+3) * LDT + row] = qv.w;
    }

    // layer_index: robust to int32 vs float32 encoding
    const int iv = li_ptr[0];
    float Lp1;
    if (iv >= 0 && iv < 1000000) Lp1 = (float)(iv + 1);
    else                         Lp1 = __int_as_float(iv) + 1.0f;
    const float a_scale = 10.0f / Lp1;
    const float inv_L   = 1.0f / Lp1;

    // Per-thread roles
    const int tm0  = (t >> 4) * 4;  // phase A: 16x16 grid, 4x4 microtile
    const int tn0  = (t & 15) * 4;
    const int irow = t >> 2;        // phase B: 4 lanes per query row
    const int cgrp = t & 3;         // each owns d = cgrp*25 .. +24

    float mrow = -INFINITY, lrow = 0.0f;
    float oacc[25];
    #pragma unroll
    for (int d = 0; d < 25; d++) oacc[d] = 0.0f;

    for (int kt = 0; kt < S_ / 64; kt++) {
        const int s0 = kt * 64;
        __syncthreads();  // previous iteration's Ss/Vs reads done

        // Load K (transposed) + V (grouped-padded) via LDG.128
        for (int idx4 = t; idx4 < NF4; idx4 += 256) {
            const int j  = idx4 / 25;       // key row in tile
            const int d0 = (idx4 - j * 25) * 4;
            const float4 kv = *(const float4*)(kbase + (size_t)(s0 + j) * D_ + d0);
            const float4 vv = *(const float4*)(vbase + (size_t)(s0 + j) * D_ + d0);
            Kt[(d0+0) * LDT + j] = kv.x;
            Kt[(d0+1) * LDT + j] = kv.y;
            Kt[(d0+2) * LDT + j] = kv.z;
            Kt[(d0+3) * LDT + j] = kv.w;
            const float ve[4] = {vv.x, vv.y, vv.z, vv.w};
            #pragma unroll
            for (int e = 0; e < 4; e++) {
                const int d = d0 + e;
                const int g = d / 25;
                Vs[j * VLD + g * 28 + (d - g * 25)] = ve[e];
            }
        }
        if (t < 64)
            bias[t] = alibi[(size_t)bh * S_ + s0 + t] * inv_L
                    + mask [(size_t)b  * S_ + s0 + t];
        __syncthreads();

        // Phase A: S tile (64x64), 4x4 per thread, LDS.128 feeds
        float sac[4][4];
        #pragma unroll
        for (int ii = 0; ii < 4; ii++)
            #pragma unroll
            for (int jj = 0; jj < 4; jj++) sac[ii][jj] = 0.0f;

        #pragma unroll 4
        for (int d = 0; d < D_; d++) {
            float4 qv = *(const float4*)&Qt[d * LDT + tm0];
            float4 kv = *(const float4*)&Kt[d * LDT + tn0];
            const float qf[4] = {qv.x, qv.y, qv.z, qv.w};
            const float kf[4] = {kv.x, kv.y, kv.z, kv.w};
            #pragma unroll
            for (int ii = 0; ii < 4; ii++)
                #pragma unroll
                for (int jj = 0; jj < 4; jj++)
                    sac[ii][jj] = fmaf(qf[ii], kf[jj], sac[ii][jj]);
        }
        {
            float bf[4];
            #pragma unroll
            for (int jj = 0; jj < 4; jj++) bf[jj] = bias[tn0 + jj];
            #pragma unroll
            for (int ii = 0; ii < 4; ii++) {
                float4 sv;
                sv.x = sac[ii][0] * a_scale + bf[0];
                sv.y = sac[ii][1] * a_scale + bf[1];
                sv.z = sac[ii][2] * a_scale + bf[2];
                sv.w = sac[ii][3] * a_scale + bf[3];
                *(float4*)&Ss[(tm0 + ii) * LDS_ + tn0] = sv;
            }
        }
        __syncthreads();

        // Phase B: online softmax + PV. 4 consecutive lanes own one row.
        float tmax = -INFINITY;
        #pragma unroll
        for (int qq = 0; qq < 16; qq++)
            tmax = fmaxf(tmax, Ss[irow * LDS_ + cgrp * 16 + qq]);
        tmax = fmaxf(tmax, __shfl_xor_sync(0xffffffffu, tmax, 1));
        tmax = fmaxf(tmax, __shfl_xor_sync(0xffffffffu, tmax, 2));

        const float mnew = fmaxf(mrow, tmax);
        const float corr = __expf(mrow - mnew);
        float psum = 0.0f;
        #pragma unroll
        for (int qq = 0; qq < 16; qq++) {
            const int off = irow * LDS_ + cgrp * 16 + qq;
            const float p = __expf(Ss[off] - mnew);
            Ss[off] = p;
            psum += p;
        }
        psum += __shfl_xor_sync(0xffffffffu, psum, 1);
        psum += __shfl_xor_sync(0xffffffffu, psum, 2);

        lrow = lrow * corr + psum;
        mrow = mnew;
        #pragma unroll
        for (int d = 0; d < 25; d++) oacc[d] *= corr;
        __syncwarp();  // row's 4 lanes see each other's P writes

        const float* vg = &Vs[cgrp * 28];
        #pragma unroll 2
        for (int j = 0; j < 64; j++) {
            const float p = Ss[irow * LDS_ + j];
            const float* vrow = vg + j * VLD;
            #pragma unroll
            for (int q = 0; q < 6; q++) {
                float4 vv = *(const float4*)(vrow + q * 4);
                oacc[q*4+0] = fmaf(p, vv.x, oacc[q*4+0]);
                oacc[q*4+1] = fmaf(p, vv.y, oacc[q*4+1]);
                oacc[q*4+2] = fmaf(p, vv.z, oacc[q*4+2]);
                oacc[q*4+3] = fmaf(p, vv.w, oacc[q*4+3]);
            }
            oacc[24] = fmaf(p, vrow[24], oacc[24]);
        }
    }

    const float invl = 1.0f / lrow;
    float* obase = g_ao + (size_t)bh * S_ * D_ + (size_t)(q0 + irow) * D_ + cgrp * 25;
    #pragma unroll
    for (int d = 0; d < 25; d++) obase[d] = oacc[d] * invl;
}

// ---------------------------------------------------------------------------
// Launch
// inputs: x, alibi, attention_mask, wq, wk, wv, wo, layer_index
// ---------------------------------------------------------------------------
#define FLASH_SMEM_BYTES ((2*D_*LDT + 64*VLD + 64*LDS_ + 64) * (int)sizeof(float))

extern "C" void kernel_launch(void* const* d_in, const int* in_sizes, int n_in,
                              void* d_out, int out_size)
{
    const float* x     = (const float*)d_in[0];
    const float* alibi = (const float*)d_in[1];
    const float* amask = (const float*)d_in[2];
    const float* wq    = (const float*)d_in[3];
    const float* wk    = (const float*)d_in[4];
    const float* wv    = (const float*)d_in[5];
    const float* wo    = (const float*)d_in[6];
    const int*   li    = (const int*)  d_in[7];
    float* out = (float*)d_out;

    float *qp, *kp, *vp, *aop;
    cudaGetSymbolAddress((void**)&qp,  g_q);
    cudaGetSymbolAddress((void**)&kp,  g_k);
    cudaGetSymbolAddress((void**)&vp,  g_v);
    cudaGetSymbolAddress((void**)&aop, g_ao);

    cudaFuncSetAttribute(flash_kernel,
                         cudaFuncAttributeMaxDynamicSharedMemorySize,
                         FLASH_SMEM_BYTES);

    const dim3 qkvGrid((HID_ + BN - 1) / BN, M_ / BM, 3);  // (10, 64, 3)
    const dim3 outGrid((HID_ + BN - 1) / BN, M_ / BM);     // (10, 64)

    gemm_qkv_kernel<<<qkvGrid, 256>>>(x, wq, wk, wv, qp, kp, vp);

    flash_kernel<<<dim3(S_ / 64, B_ * H_), 256, FLASH_SMEM_BYTES>>>(alibi, amask, li);

    gemm_tn_kernel<<<outGrid, 256>>>(aop, wo, out);
}

// round 12
// speedup vs baseline: 1.0327x; 1.0327x over previous
#include <cuda_runtime.h>
#include <math.h>

// Problem constants
#define B_   4
#define S_   2048
#define H_   12
#define D_   100
#define HID_ 1200
#define M_   (B_*S_)   // 8192

// Scratch (allocation-free rule: __device__ globals)
__device__ float g_q [B_*H_*S_*D_];
__device__ float g_k [B_*H_*S_*D_];
__device__ float g_v [B_*H_*S_*D_];
__device__ float g_ao[B_*H_*S_*D_];

// ---------------------------------------------------------------------------
// GEMM (TN): C[m,n] = sum_k A[m,k] * W[n,k]
// A: (M_, HID_) row-major, W: (HID_, HID_) row-major.
// 128x128x16 tiles, 256 threads, 8x8 microtile (n split as 4+4 at distance
// 64 -> Bs LDS.128 reads hit bank groups 0-7 exactly once per phase:
// conflict-free; round-5 ncu showed L1=90% from the old 32B-stride pattern).
// Double-buffered smem, 1 __syncthreads per 16-K slice.
// qkv_mode=1: scatter output into (b,h,s,d) layout. mode=0: plain row-major.
// ---------------------------------------------------------------------------
#define BM 128
#define BN 128
#define BKg 16

__device__ __forceinline__ void gemm_tn_body(
    const float* __restrict__ A, const float* __restrict__ W,
    float* __restrict__ dst, int qkv_mode)
{
    __shared__ __align__(16) float As[2][BKg][BM];
    __shared__ __align__(16) float Bs[2][BKg][BN];

    const int K = HID_, N = HID_;
    const int t  = threadIdx.x;
    const int m0 = blockIdx.y * BM;
    const int n0 = blockIdx.x * BN;

    // Tile load mapping: 128 rows x 16 cols = 512 float4 per array,
    // 2 per thread: row = t>>1, col segments seg and seg+8 (seg = (t&1)*4).
    const int ldRow = t >> 1;        // 0..127
    const int ldSeg = (t & 1) * 4;   // 0 or 4

    // Microtile mapping: m = 8 contiguous rows (As reads broadcast);
    // n = two 4-wide groups at tn0 and tn0+64 (conflict-free Bs reads).
    const int tm0 = (t >> 4) * 8;    // 0,8,...,120
    const int tn0 = (t & 15) * 4;    // 0,4,...,60

    float acc[8][8];
    #pragma unroll
    for (int i = 0; i < 8; i++)
        #pragma unroll
        for (int j = 0; j < 8; j++) acc[i][j] = 0.0f;

    const bool bValid = (n0 + ldRow) < N;
    const float* aPtr = A + (size_t)(m0 + ldRow) * K + ldSeg;
    const float* bPtr = W + (size_t)(n0 + ldRow) * K + ldSeg;

    float4 av0, av1, bv0, bv1;

    // Prime buffer 0
    av0 = *(const float4*)(aPtr);
    av1 = *(const float4*)(aPtr + 8);
    bv0 = make_float4(0.f, 0.f, 0.f, 0.f);
    bv1 = bv0;
    if (bValid) {
        bv0 = *(const float4*)(bPtr);
        bv1 = *(const float4*)(bPtr + 8);
    }
    {
        const float ae0[4] = {av0.x, av0.y, av0.z, av0.w};
        const float ae1[4] = {av1.x, av1.y, av1.z, av1.w};
        const float be0[4] = {bv0.x, bv0.y, bv0.z, bv0.w};
        const float be1[4] = {bv1.x, bv1.y, bv1.z, bv1.w};
        #pragma unroll
        for (int e = 0; e < 4; e++) {
            As[0][ldSeg + e][ldRow]     = ae0[e];
            As[0][ldSeg + 8 + e][ldRow] = ae1[e];
            Bs[0][ldSeg + e][ldRow]     = be0[e];
            Bs[0][ldSeg + 8 + e][ldRow] = be1[e];
        }
    }
    __syncthreads();

    int buf = 0;
    for (int k0 = 0; k0 < K; k0 += BKg) {
        const bool hasNext = (k0 + BKg) < K;
        if (hasNext) {
            av0 = *(const float4*)(aPtr + k0 + BKg);
            av1 = *(const float4*)(aPtr + k0 + BKg + 8);
            if (bValid) {
                bv0 = *(const float4*)(bPtr + k0 + BKg);
                bv1 = *(const float4*)(bPtr + k0 + BKg + 8);
            }
        }

        #pragma unroll
        for (int kk = 0; kk < BKg; kk++) {
            float ra[8], rb[8];
            *(float4*)(ra)     = *(const float4*)&As[buf][kk][tm0];
            *(float4*)(ra + 4) = *(const float4*)&As[buf][kk][tm0 + 4];
            *(float4*)(rb)     = *(const float4*)&Bs[buf][kk][tn0];
            *(float4*)(rb + 4) = *(const float4*)&Bs[buf][kk][tn0 + 64];
            #pragma unroll
            for (int i = 0; i < 8; i++)
                #pragma unroll
                for (int j = 0; j < 8; j++)
                    acc[i][j] = fmaf(ra[i], rb[j], acc[i][j]);
        }

        if (hasNext) {
            const int nb = buf ^ 1;
            const float ae0[4] = {av0.x, av0.y, av0.z, av0.w};
            const float ae1[4] = {av1.x, av1.y, av1.z, av1.w};
            const float be0[4] = {bv0.x, bv0.y, bv0.z, bv0.w};
            const float be1[4] = {bv1.x, bv1.y, bv1.z, bv1.w};
            #pragma unroll
            for (int e = 0; e < 4; e++) {
                As[nb][ldSeg + e][ldRow]     = ae0[e];
                As[nb][ldSeg + 8 + e][ldRow] = ae1[e];
                Bs[nb][ldSeg + e][ldRow]     = be0[e];
                Bs[nb][ldSeg + 8 + e][ldRow] = be1[e];
            }
        }
        __syncthreads();
        buf ^= 1;
    }

    // Store: j 0..3 -> columns n0+tn0+j ; j 4..7 -> columns n0+64+tn0+(j-4)
    #pragma unroll
    for (int i = 0; i < 8; i++) {
        const int m = m0 + tm0 + i;
        #pragma unroll
        for (int j = 0; j < 8; j++) {
            const int n = n0 + tn0 + ((j < 4) ? j : (64 + j - 4));
            if (n < N) {
                const float v = acc[i][j];
                if (qkv_mode) {
                    const int b = m >> 11;          // S_ = 2048
                    const int s = m & (S_ - 1);
                    const int h = n / D_;
                    const int d = n - h * D_;
                    dst[(((size_t)(b * H_ + h)) * S_ + s) * D_ + d] = v;
                } else {
                    dst[(size_t)m * N + n] = v;
                }
            }
        }
    }
}

// Fused QKV: gridDim.z = 3 selects {wq->g_q, wk->g_k, wv->g_v}
__global__ __launch_bounds__(256, 2)
void gemm_qkv_kernel(const float* __restrict__ A,
                     const float* __restrict__ wq,
                     const float* __restrict__ wk,
                     const float* __restrict__ wv,
                     float* __restrict__ qdst,
                     float* __restrict__ kdst,
                     float* __restrict__ vdst)
{
    const int z = blockIdx.z;
    const float* W = (z == 0) ? wq : (z == 1) ? wk : wv;
    float* dst     = (z == 0) ? qdst : (z == 1) ? kdst : vdst;
    gemm_tn_body(A, W, dst, 1);
}

// Plain single GEMM (output projection)
__global__ __launch_bounds__(256, 2)
void gemm_tn_kernel(const float* __restrict__ A, const float* __restrict__ W,
                    float* __restrict__ dst)
{
    gemm_tn_body(A, W, dst, 0);
}

// ---------------------------------------------------------------------------
// Flash attention (fp32, online softmax).
// grid: (S_/64, B_*H_), block: 256 threads.
// S = qk * (10/L) + alibi/L + mask   (sqrt(D)=10, L = layer_index+1)
// Output written in (b,h,s,d) C-order == the reference's raw reshape layout.
//
// Smem layouts (hot-loop accesses LDS.128/STS.128, bank behavior verified):
//  Qt,Kt : transposed, leading dim 68 (16B-aligned float4 microtile bases)
//  Vs    : rows of 4 padded 28-float groups (stride 112); lane cgrp's 25
//          columns (d = cgrp*25 ..+24) start at float offset cgrp*28
//  Ss    : 64x68 score tile (stride 68 -> STS.128 epilogue conflict-free)
// ---------------------------------------------------------------------------
#define LDT  68   // transposed Q/K smem leading dim
#define LDS_ 68   // score tile leading dim
#define VLD  112  // V smem row stride (4 groups x 28)
#define NF4  (64 * D_ / 4)   // 1600 float4 per 64x100 tile

__global__ __launch_bounds__(256)
void flash_kernel(const float* __restrict__ alibi,
                  const float* __restrict__ mask,
                  const int*   __restrict__ li_ptr)
{
    extern __shared__ float sm[];
    float* Qt   = sm;                   // [100][68]
    float* Kt   = Qt + D_ * LDT;        // [100][68]
    float* Vs   = Kt + D_ * LDT;        // [64][112]
    float* Ss   = Vs + 64 * VLD;        // [64][68]
    float* bias = Ss + 64 * LDS_;       // [64]

    const int t  = threadIdx.x;
    const int bh = blockIdx.y;
    const int b  = bh / H_;
    const int q0 = blockIdx.x * 64;

    const float* qbase = g_q + (size_t)bh * S_ * D_;
    const float* kbase = g_k + (size_t)bh * S_ * D_;
    const float* vbase = g_v + (size_t)bh * S_ * D_;

    // Load Q tile transposed via LDG.128: Qt[d][i]
    for (int idx4 = t; idx4 < NF4; idx4 += 256) {
        const int row = idx4 / 25;          // query row in tile
        const int d0  = (idx4 - row * 25) * 4;
        const float4 qv = *(const float4*)(qbase + (size_t)(q0 + row) * D_ + d0);
        Qt[(d0+0) * LDT + row] = qv.x;
        Qt[(d0+1) * LDT + row] = qv.y;
        Qt[(d0+2) * LDT + row] = qv.z;
        Qt[(d0+3) * LDT + row] = qv.w;
    }

    // layer_index: robust to int32 vs float32 encoding
    const int iv = li_ptr[0];
    float Lp1;
    if (iv >= 0 && iv < 1000000) Lp1 = (float)(iv + 1);
    else                         Lp1 = __int_as_float(iv) + 1.0f;
    const float a_scale = 10.0f / Lp1;
    const float inv_L   = 1.0f / Lp1;

    // Per-thread roles
    const int tm0  = (t >> 4) * 4;  // phase A: 16x16 grid, 4x4 microtile
    const int tn0  = (t & 15) * 4;
    const int irow = t >> 2;        // phase B: 4 lanes per query row
    const int cgrp = t & 3;         // each owns d = cgrp*25 .. +24

    float mrow = -INFINITY, lrow = 0.0f;
    float oacc[25];
    #pragma unroll
    for (int d = 0; d < 25; d++) oacc[d] = 0.0f;

    for (int kt = 0; kt < S_ / 64; kt++) {
        const int s0 = kt * 64;
        __syncthreads();  // previous iteration's Ss/Vs reads done

        // Load K (transposed) + V (grouped-padded) via LDG.128
        for (int idx4 = t; idx4 < NF4; idx4 += 256) {
            const int j  = idx4 / 25;       // key row in tile
            const int d0 = (idx4 - j * 25) * 4;
            const float4 kv = *(const float4*)(kbase + (size_t)(s0 + j) * D_ + d0);
            const float4 vv = *(const float4*)(vbase + (size_t)(s0 + j) * D_ + d0);
            Kt[(d0+0) * LDT + j] = kv.x;
            Kt[(d0+1) * LDT + j] = kv.y;
            Kt[(d0+2) * LDT + j] = kv.z;
            Kt[(d0+3) * LDT + j] = kv.w;
            const float ve[4] = {vv.x, vv.y, vv.z, vv.w};
            #pragma unroll
            for (int e = 0; e < 4; e++) {
                const int d = d0 + e;
                const int g = d / 25;
                Vs[j * VLD + g * 28 + (d - g * 25)] = ve[e];
            }
        }
        if (t < 64)
            bias[t] = alibi[(size_t)bh * S_ + s0 + t] * inv_L
                    + mask [(size_t)b  * S_ + s0 + t];
        __syncthreads();

        // Phase A: S tile (64x64), 4x4 per thread, LDS.128 feeds
        float sac[4][4];
        #pragma unroll
        for (int ii = 0; ii < 4; ii++)
            #pragma unroll
            for (int jj = 0; jj < 4; jj++) sac[ii][jj] = 0.0f;

        #pragma unroll 4
        for (int d = 0; d < D_; d++) {
            float4 qv = *(const float4*)&Qt[d * LDT + tm0];
            float4 kv = *(const float4*)&Kt[d * LDT + tn0];
            const float qf[4] = {qv.x, qv.y, qv.z, qv.w};
            const float kf[4] = {kv.x, kv.y, kv.z, kv.w};
            #pragma unroll
            for (int ii = 0; ii < 4; ii++)
                #pragma unroll
                for (int jj = 0; jj < 4; jj++)
                    sac[ii][jj] = fmaf(qf[ii], kf[jj], sac[ii][jj]);
        }
        {
            float bf[4];
            #pragma unroll
            for (int jj = 0; jj < 4; jj++) bf[jj] = bias[tn0 + jj];
            #pragma unroll
            for (int ii = 0; ii < 4; ii++) {
                float4 sv;
                sv.x = sac[ii][0] * a_scale + bf[0];
                sv.y = sac[ii][1] * a_scale + bf[1];
                sv.z = sac[ii][2] * a_scale + bf[2];
                sv.w = sac[ii][3] * a_scale + bf[3];
                *(float4*)&Ss[(tm0 + ii) * LDS_ + tn0] = sv;
            }
        }
        __syncthreads();

        // Phase B: online softmax + PV. 4 consecutive lanes own one row.
        float tmax = -INFINITY;
        #pragma unroll
        for (int qq = 0; qq < 16; qq++)
            tmax = fmaxf(tmax, Ss[irow * LDS_ + cgrp * 16 + qq]);
        tmax = fmaxf(tmax, __shfl_xor_sync(0xffffffffu, tmax, 1));
        tmax = fmaxf(tmax, __shfl_xor_sync(0xffffffffu, tmax, 2));

        const float mnew = fmaxf(mrow, tmax);
        const float corr = __expf(mrow - mnew);
        float psum = 0.0f;
        #pragma unroll
        for (int qq = 0; qq < 16; qq++) {
            const int off = irow * LDS_ + cgrp * 16 + qq;
            const float p = __expf(Ss[off] - mnew);
            Ss[off] = p;
            psum += p;
        }
        psum += __shfl_xor_sync(0xffffffffu, psum, 1);
        psum += __shfl_xor_sync(0xffffffffu, psum, 2);

        lrow = lrow * corr + psum;
        mrow = mnew;
        #pragma unroll
        for (int d = 0; d < 25; d++) oacc[d] *= corr;
        __syncwarp();  // row's 4 lanes see each other's P writes

        const float* vg = &Vs[cgrp * 28];
        #pragma unroll 2
        for (int j = 0; j < 64; j++) {
            const float p = Ss[irow * LDS_ + j];
            const float* vrow = vg + j * VLD;
            #pragma unroll
            for (int q = 0; q < 6; q++) {
                float4 vv = *(const float4*)(vrow + q * 4);
                oacc[q*4+0] = fmaf(p, vv.x, oacc[q*4+0]);
                oacc[q*4+1] = fmaf(p, vv.y, oacc[q*4+1]);
                oacc[q*4+2] = fmaf(p, vv.z, oacc[q*4+2]);
                oacc[q*4+3] = fmaf(p, vv.w, oacc[q*4+3]);
            }
            oacc[24] = fmaf(p, vrow[24], oacc[24]);
        }
    }

    const float invl = 1.0f / lrow;
    float* obase = g_ao + (size_t)bh * S_ * D_ + (size_t)(q0 + irow) * D_ + cgrp * 25;
    #pragma unroll
    for (int d = 0; d < 25; d++) obase[d] = oacc[d] * invl;
}

// ---------------------------------------------------------------------------
// Launch
// inputs: x, alibi, attention_mask, wq, wk, wv, wo, layer_index
// ---------------------------------------------------------------------------
#define FLASH_SMEM_BYTES ((2*D_*LDT + 64*VLD + 64*LDS_ + 64) * (int)sizeof(float))

extern "C" void kernel_launch(void* const* d_in, const int* in_sizes, int n_in,
                              void* d_out, int out_size)
{
    const float* x     = (const float*)d_in[0];
    const float* alibi = (const float*)d_in[1];
    const float* amask = (const float*)d_in[2];
    const float* wq    = (const float*)d_in[3];
    const float* wk    = (const float*)d_in[4];
    const float* wv    = (const float*)d_in[5];
    const float* wo    = (const float*)d_in[6];
    const int*   li    = (const int*)  d_in[7];
    float* out = (float*)d_out;

    float *qp, *kp, *vp, *aop;
    cudaGetSymbolAddress((void**)&qp,  g_q);
    cudaGetSymbolAddress((void**)&kp,  g_k);
    cudaGetSymbolAddress((void**)&vp,  g_v);
    cudaGetSymbolAddress((void**)&aop, g_ao);

    cudaFuncSetAttribute(flash_kernel,
                         cudaFuncAttributeMaxDynamicSharedMemorySize,
                         FLASH_SMEM_BYTES);

    const dim3 qkvGrid((HID_ + BN - 1) / BN, M_ / BM, 3);  // (10, 64, 3)
    const dim3 outGrid((HID_ + BN - 1) / BN, M_ / BM);     // (10, 64)

    gemm_qkv_kernel<<<qkvGrid, 256>>>(x, wq, wk, wv, qp, kp, vp);

    flash_kernel<<<dim3(S_ / 64, B_ * H_), 256, FLASH_SMEM_BYTES>>>(alibi, amask, li);

    gemm_tn_kernel<<<outGrid, 256>>>(aop, wo, out);
}